// round 12
// baseline (speedup 1.0000x reference)
#include <cuda_runtime.h>
#include <cstdint>

// Quantized SiLU (per-row scales), S=8192 rows, H=4096 cols.
//   x_f   = x * scale_x[row]
//   y_q   = clip(rint(sigmoid(x_f) / scale_y[row]), -127, 127)
//   y_f   = y_q * scale_y[row]
//   out_q = clip(rint((x_f * y_f) / scale_out[row]), -127, 127)
//
// x is int8-valued => only 255 distinct inputs per row; per-CTA shared-mem
// LUT turns the 4096-element row into index+LDS work.
//
// R12 structure: 2 rows per 256-thread CTA (4096 CTAs).
//  - 8 front-batched int4 loads per thread (4 per row) -> keeps the measured
//    optimum of ~256 outstanding loads/SM (R10's winning profile).
//  - ONE barrier covers a dual LUT (row0 at lut[0..254], row1 at
//    lut[256..510]); each thread builds 2 independent entries (good ILP).
//    Halves the per-row LUT-build + barrier critical path and halves
//    CTA-scheduling overhead vs 8192 CTAs.
//
// x arrives promoted to a 4-byte type (int32 or float32); values always in
// [-127,127], so the index decodes per element branch-free.
// Output: float32 [S*H out_q values][S scale_out values].

#define LOG2E 1.44269504088896340736f

// word -> LUT index in [0,254]
__device__ __forceinline__ int decode_idx(int w) {
    float fi = (float)w;                              // int32 interpretation
    int   wf = __float2int_rn(__int_as_float(w));     // float32 interpretation
    return ((fabsf(fi) > 127.5f) ? wf : w) + 127;
}

__device__ __forceinline__ float lut_entry(int i, float scale_x, float scale_y,
                                           float scale_o) {
    float f   = (float)(i - 127);
    float xf  = f * scale_x;
    float e   = exp2f(-xf * LOG2E);                   // exp(-x_f)
    float sig = __frcp_rn(1.0f + e);                  // sigmoid(x_f)
    float yq  = fminf(rintf(sig / scale_y), 127.0f);  // sigmoid>0: upper clip only
    float oq  = rintf(xf * (yq * scale_y) / scale_o);
    return fminf(fmaxf(oq, -127.0f), 127.0f);
}

__global__ void __launch_bounds__(256) silu_lut2_kernel(
    const int4* __restrict__ x,
    const float* __restrict__ scale_x_v,
    const float* __restrict__ scale_y_v,
    const float* __restrict__ scale_out_v,
    float4* __restrict__ out,
    float* __restrict__ tail_dst,
    int write_tail)
{
    __shared__ float lut[512];         // [0..254]: row0, [256..510]: row1
    int row0 = blockIdx.x * 2;
    int t = threadIdx.x;

    long base = (long)row0 * 1024 + t;   // int4 index

    // front-batch both rows' loads (8 in flight during dual LUT build)
    int4 a0 = __ldcs(x + base);
    int4 a1 = __ldcs(x + base + 256);
    int4 a2 = __ldcs(x + base + 512);
    int4 a3 = __ldcs(x + base + 768);
    int4 b0 = __ldcs(x + base + 1024);
    int4 b1 = __ldcs(x + base + 1280);
    int4 b2 = __ldcs(x + base + 1536);
    int4 b3 = __ldcs(x + base + 1792);

    float sx0 = __ldg(&scale_x_v[row0]);
    float sy0 = __ldg(&scale_y_v[row0]);
    float so0 = __ldg(&scale_out_v[row0]);
    float sx1 = __ldg(&scale_x_v[row0 + 1]);
    float sy1 = __ldg(&scale_y_v[row0 + 1]);
    float so1 = __ldg(&scale_out_v[row0 + 1]);

    // build both LUTs: thread t builds entry t of each row (2 independent chains)
    if (t < 255) {
        lut[t]       = lut_entry(t, sx0, sy0, so0);
        lut[t + 256] = lut_entry(t, sx1, sy1, so1);
    }
    if (write_tail && t < 2) tail_dst[row0 + t] = (t == 0) ? so0 : so1;
    __syncthreads();

    float4 r;
    r.x = lut[decode_idx(a0.x)]; r.y = lut[decode_idx(a0.y)];
    r.z = lut[decode_idx(a0.z)]; r.w = lut[decode_idx(a0.w)];
    __stcs(out + base, r);
    r.x = lut[decode_idx(a1.x)]; r.y = lut[decode_idx(a1.y)];
    r.z = lut[decode_idx(a1.z)]; r.w = lut[decode_idx(a1.w)];
    __stcs(out + base + 256, r);
    r.x = lut[decode_idx(a2.x)]; r.y = lut[decode_idx(a2.y)];
    r.z = lut[decode_idx(a2.z)]; r.w = lut[decode_idx(a2.w)];
    __stcs(out + base + 512, r);
    r.x = lut[decode_idx(a3.x)]; r.y = lut[decode_idx(a3.y)];
    r.z = lut[decode_idx(a3.z)]; r.w = lut[decode_idx(a3.w)];
    __stcs(out + base + 768, r);

    r.x = lut[256 + decode_idx(b0.x)]; r.y = lut[256 + decode_idx(b0.y)];
    r.z = lut[256 + decode_idx(b0.z)]; r.w = lut[256 + decode_idx(b0.w)];
    __stcs(out + base + 1024, r);
    r.x = lut[256 + decode_idx(b1.x)]; r.y = lut[256 + decode_idx(b1.y)];
    r.z = lut[256 + decode_idx(b1.z)]; r.w = lut[256 + decode_idx(b1.w)];
    __stcs(out + base + 1280, r);
    r.x = lut[256 + decode_idx(b2.x)]; r.y = lut[256 + decode_idx(b2.y)];
    r.z = lut[256 + decode_idx(b2.z)]; r.w = lut[256 + decode_idx(b2.w)];
    __stcs(out + base + 1536, r);
    r.x = lut[256 + decode_idx(b3.x)]; r.y = lut[256 + decode_idx(b3.y)];
    r.z = lut[256 + decode_idx(b3.z)]; r.w = lut[256 + decode_idx(b3.w)];
    __stcs(out + base + 1792, r);
}

// Generic fallback for unexpected shapes (direct evaluation).
__device__ __forceinline__ float decode_elem(int w) {
    float fi = (float)w;
    float ff = __int_as_float(w);
    return (fabsf(fi) > 127.5f) ? ff : fi;
}

__global__ void __launch_bounds__(256) silu_quant_generic_kernel(
    const int* __restrict__ x,
    const float* __restrict__ scale_x_v,
    const float* __restrict__ scale_y_v,
    const float* __restrict__ scale_out_v,
    float* __restrict__ out,
    int H, long total)
{
    long i = (long)blockIdx.x * blockDim.x + threadIdx.x;
    if (i >= total) return;
    int row = (int)(i / H);
    float scale_x = scale_x_v[row];
    float scale_y = scale_y_v[row];
    float f   = decode_elem(x[i]);
    float xf  = f * scale_x;
    float e   = exp2f(-xf * LOG2E);
    float sig = __frcp_rn(1.0f + e);
    float yq  = fminf(rintf(sig / scale_y), 127.0f);
    float oq  = rintf(xf * (yq * scale_y) / scale_out_v[row]);
    out[i] = fminf(fmaxf(oq, -127.0f), 127.0f);
}

__global__ void tail_pad_kernel(const float* __restrict__ scale_o,
                                float* __restrict__ dst, int S, long extra) {
    long i = (long)blockIdx.x * blockDim.x + threadIdx.x;
    if (i >= extra) return;
    dst[i] = (i < S) ? scale_o[i] : 0.0f;
}

extern "C" void kernel_launch(void* const* d_in, const int* in_sizes, int n_in,
                              void* d_out, int out_size) {
    const void* x         = d_in[0];
    const float* scale_x  = (const float*)d_in[1];
    const float* scale_y  = (const float*)d_in[2];
    const float* scale_o  = (const float*)d_in[3];

    int S = in_sizes[1];            // rows (scale_x element count)
    int H = in_sizes[0] / S;        // cols
    long total = (long)S * H;
    long extra = (long)out_size - total;
    float* out = (float*)d_out;

    if (H == 4096 && (S & 1) == 0) {
        int write_tail = (extra >= (long)S) ? 1 : 0;
        silu_lut2_kernel<<<S / 2, 256>>>(
            (const int4*)x, scale_x, scale_y, scale_o,
            (float4*)out, out + total, write_tail);
        if (extra > (long)S) {
            long pad = extra - S;
            tail_pad_kernel<<<(int)((pad + 255) / 256), 256>>>(
                scale_o + S, out + total + S, 0, pad);
        } else if (extra > 0 && !write_tail) {
            tail_pad_kernel<<<(int)((extra + 255) / 256), 256>>>(
                scale_o, out + total, (int)extra, extra);
        }
    } else {
        long blocks = (total + 255) / 256;
        silu_quant_generic_kernel<<<(unsigned)blocks, 256>>>(
            (const int*)x, scale_x, scale_y, scale_o, out, H, total);
        if (extra > 0) {
            tail_pad_kernel<<<(int)((extra + 255) / 256), 256>>>(
                scale_o, out + total, (int)(extra < S ? extra : S), extra);
        }
    }
}

// round 13
// speedup vs baseline: 1.0092x; 1.0092x over previous
#include <cuda_runtime.h>
#include <cstdint>

// Quantized SiLU (per-row scales), S=8192 rows, H=4096 cols.
//   x_f   = x * scale_x[row]
//   y_q   = clip(rint(sigmoid(x_f) / scale_y[row]), -127, 127)
//   y_f   = y_q * scale_y[row]
//   out_q = clip(rint((x_f * y_f) / scale_out[row]), -127, 127)
//
// x is int8-valued => only 255 distinct inputs per row; per-CTA shared-mem
// LUT turns each element into index+LDS work.
//
// R13 structure — break the register-vs-MLP trade with cp.async:
//   R7..R12 measured: 8 outstanding LDG.128 = 32 payload regs -> occ 50%;
//   4 outstanding = occ 69% but less MLP. cp.async (LDGSTS) stages the row
//   global->shared with ZERO payload registers and no depth cap: deep MLP
//   AND high occupancy simultaneously. Each thread stages its own 4 int4s,
//   LUT build overlaps the copies, then LDS.128 + 4 lookups + STG.128 per k.
//
// x arrives promoted to a 4-byte type (int32 or float32); values always in
// [-127,127], so the index decodes per element branch-free.
// Output: float32 [S*H out_q values][S scale_out values].

#define LOG2E 1.44269504088896340736f

// word -> LUT index in [0,254]
__device__ __forceinline__ int decode_idx(int w) {
    float fi = (float)w;                              // int32 interpretation
    int   wf = __float2int_rn(__int_as_float(w));     // float32 interpretation
    return ((fabsf(fi) > 127.5f) ? wf : w) + 127;
}

__device__ __forceinline__ float lut_entry(int i, float scale_x, float scale_y,
                                           float scale_o) {
    float f   = (float)(i - 127);
    float xf  = f * scale_x;
    float e   = exp2f(-xf * LOG2E);                   // exp(-x_f)
    float sig = __frcp_rn(1.0f + e);                  // sigmoid(x_f)
    float yq  = fminf(rintf(sig / scale_y), 127.0f);  // sigmoid>0: upper clip only
    float oq  = rintf(xf * (yq * scale_y) / scale_o);
    return fminf(fmaxf(oq, -127.0f), 127.0f);
}

__global__ void __launch_bounds__(256) silu_cpasync_kernel(
    const int4* __restrict__ x,
    const float* __restrict__ scale_x_v,
    const float* __restrict__ scale_y_v,
    const float* __restrict__ scale_out_v,
    float4* __restrict__ out,
    float* __restrict__ tail_dst,
    int write_tail)
{
    __shared__ float lut[256];
    __shared__ int4  stage[1024];      // full 16KB row
    int row = blockIdx.x;
    int t = threadIdx.x;

    long base = (long)row * 1024 + t;  // int4 index

    // Stage the row global->shared with cp.async: no payload registers,
    // unbounded in-flight depth. Thread t stages stage[t + 256k].
    {
        unsigned sa = (unsigned)__cvta_generic_to_shared(&stage[t]);
        const int4* g = x + base;
        #pragma unroll
        for (int k = 0; k < 4; k++) {
            asm volatile(
                "cp.async.cg.shared.global [%0], [%1], 16;"
                :: "r"(sa + k * 4096u), "l"(g + k * 256)
                : "memory");
        }
        asm volatile("cp.async.commit_group;" ::: "memory");
    }

    float scale_x = __ldg(&scale_x_v[row]);
    float scale_y = __ldg(&scale_y_v[row]);
    float scale_o = __ldg(&scale_out_v[row]);

    // LUT build overlaps the async copies.
    if (t < 255)
        lut[t] = lut_entry(t, scale_x, scale_y, scale_o);
    if (write_tail && t == 0) tail_dst[row] = scale_o;

    asm volatile("cp.async.wait_group 0;" ::: "memory");
    __syncthreads();   // LUT visibility (each thread reads only its own staged data)

    #pragma unroll
    for (int k = 0; k < 4; k++) {
        int4 v = stage[t + 256 * k];
        float4 r;
        r.x = lut[decode_idx(v.x)];
        r.y = lut[decode_idx(v.y)];
        r.z = lut[decode_idx(v.z)];
        r.w = lut[decode_idx(v.w)];
        __stcs(out + base + 256 * k, r);
    }
}

// Generic fallback for unexpected shapes (direct evaluation).
__device__ __forceinline__ float decode_elem(int w) {
    float fi = (float)w;
    float ff = __int_as_float(w);
    return (fabsf(fi) > 127.5f) ? ff : fi;
}

__global__ void __launch_bounds__(256) silu_quant_generic_kernel(
    const int* __restrict__ x,
    const float* __restrict__ scale_x_v,
    const float* __restrict__ scale_y_v,
    const float* __restrict__ scale_out_v,
    float* __restrict__ out,
    int H, long total)
{
    long i = (long)blockIdx.x * blockDim.x + threadIdx.x;
    if (i >= total) return;
    int row = (int)(i / H);
    float scale_x = scale_x_v[row];
    float scale_y = scale_y_v[row];
    float f   = decode_elem(x[i]);
    float xf  = f * scale_x;
    float e   = exp2f(-xf * LOG2E);
    float sig = __frcp_rn(1.0f + e);
    float yq  = fminf(rintf(sig / scale_y), 127.0f);
    float oq  = rintf(xf * (yq * scale_y) / scale_out_v[row]);
    out[i] = fminf(fmaxf(oq, -127.0f), 127.0f);
}

__global__ void tail_pad_kernel(const float* __restrict__ scale_o,
                                float* __restrict__ dst, int S, long extra) {
    long i = (long)blockIdx.x * blockDim.x + threadIdx.x;
    if (i >= extra) return;
    dst[i] = (i < S) ? scale_o[i] : 0.0f;
}

extern "C" void kernel_launch(void* const* d_in, const int* in_sizes, int n_in,
                              void* d_out, int out_size) {
    const void* x         = d_in[0];
    const float* scale_x  = (const float*)d_in[1];
    const float* scale_y  = (const float*)d_in[2];
    const float* scale_o  = (const float*)d_in[3];

    int S = in_sizes[1];            // rows (scale_x element count)
    int H = in_sizes[0] / S;        // cols
    long total = (long)S * H;
    long extra = (long)out_size - total;
    float* out = (float*)d_out;

    if (H == 4096) {
        int write_tail = (extra >= (long)S) ? 1 : 0;
        silu_cpasync_kernel<<<S, 256>>>(
            (const int4*)x, scale_x, scale_y, scale_o,
            (float4*)out, out + total, write_tail);
        if (extra > (long)S) {
            long pad = extra - S;
            tail_pad_kernel<<<(int)((pad + 255) / 256), 256>>>(
                scale_o + S, out + total + S, 0, pad);
        } else if (extra > 0 && !write_tail) {
            tail_pad_kernel<<<(int)((extra + 255) / 256), 256>>>(
                scale_o, out + total, (int)extra, extra);
        }
    } else {
        long blocks = (total + 255) / 256;
        silu_quant_generic_kernel<<<(unsigned)blocks, 256>>>(
            (const int*)x, scale_x, scale_y, scale_o, out, H, total);
        if (extra > 0) {
            tail_pad_kernel<<<(int)((extra + 255) / 256), 256>>>(
                scale_o, out + total, (int)(extra < S ? extra : S), extra);
        }
    }
}